// round 5
// baseline (speedup 1.0000x reference)
#include <cuda_runtime.h>
#include <cuda_fp16.h>
#include <cstdint>

#define B    32768
#define DIN  4096
#define H    100
#define DOUT 1000
#define BN_EPS 1e-4f

#define KC      64                 // K per chunk
#define NCHUNK  (DIN / KC)         // 64
#define NPAD    128                // padded feature rows in g_w1h

// padded smem tile geometry (fp16: 64 elems = 128B + 16B pad)
#define PITCH_B   144
#define SPLIT_SZ  (128 * PITCH_B)  // 18432
#define BUF_SZ    (3 * SPLIT_SZ)   // A-hi, A-lo, B = 55296
#define B_OFF     (2 * SPLIT_SZ)
#define SB1_OFF   (2 * BUF_SZ)     // b1 staging
#define SMEM_TOTAL (2 * BUF_SZ + 512)

// ---- scratch (no allocations allowed) ----
__device__ float     g_h[(size_t)B * H];
__device__ float     g_scale[H];
__device__ float     g_shift[H];
__device__ unsigned  g_w2p[DOUT * 4];
__device__ __half    g_w1h[(size_t)NPAD * DIN];  // sign(W1) fp16, rows 100..127 = 0
__device__ float     g_part[256 * 200];          // per-CTA BN partials [s|s2]

// ============================================================
// helpers
// ============================================================
__device__ __forceinline__ uint32_t smem_u32(const void* p) {
    uint32_t a;
    asm("{ .reg .u64 t; cvta.to.shared.u64 t, %1; cvt.u32.u64 %0, t; }"
        : "=r"(a) : "l"(p));
    return a;
}
__device__ __forceinline__ void ldsm4(uint32_t* r, uint32_t addr) {
    asm volatile("ldmatrix.sync.aligned.m8n8.x4.shared.b16 {%0,%1,%2,%3}, [%4];"
                 : "=r"(r[0]), "=r"(r[1]), "=r"(r[2]), "=r"(r[3]) : "r"(addr));
}
__device__ __forceinline__ void ldsm2(uint32_t* r, uint32_t addr) {
    asm volatile("ldmatrix.sync.aligned.m8n8.x2.shared.b16 {%0,%1}, [%2];"
                 : "=r"(r[0]), "=r"(r[1]) : "r"(addr));
}
__device__ __forceinline__ void mma16816(float* d, const uint32_t* a,
                                         const uint32_t* b) {
    asm volatile(
        "mma.sync.aligned.m16n8k16.row.col.f32.f16.f16.f32 "
        "{%0,%1,%2,%3}, {%4,%5,%6,%7}, {%8,%9}, {%0,%1,%2,%3};"
        : "+f"(d[0]), "+f"(d[1]), "+f"(d[2]), "+f"(d[3])
        : "r"(a[0]), "r"(a[1]), "r"(a[2]), "r"(a[3]), "r"(b[0]), "r"(b[1]));
}
// exact 2-way fp16 split
__device__ __forceinline__ void split2(float4 v, uint2& hi, uint2& lo) {
    __half2 a = __floats2half2_rn(v.x, v.y);
    __half2 b = __floats2half2_rn(v.z, v.w);
    float2 fa = __half22float2(a), fb = __half22float2(b);
    __half2 c = __floats2half2_rn(v.x - fa.x, v.y - fa.y);
    __half2 d = __floats2half2_rn(v.z - fb.x, v.w - fb.y);
    hi = make_uint2(*(uint32_t*)&a, *(uint32_t*)&b);
    lo = make_uint2(*(uint32_t*)&c, *(uint32_t*)&d);
}

// ============================================================
// Kernel P: fused packing of sign(W1)->fp16 and sign(W2)->bitmask
// ============================================================
__global__ void pack_all(const float* __restrict__ W1,
                         const float* __restrict__ W2) {
    int gb = blockIdx.x;
    int tid = threadIdx.x;
    if (gb < 2048) {
        int idx = gb * 256 + tid;
        int row = idx >> 12;
        int col = idx & 4095;
        float v = 0.f;
        if (row < H) v = (W1[(size_t)row * DIN + col] >= 0.f) ? 1.f : -1.f;
        g_w1h[(size_t)row * DIN + col] = __float2half(v);
    } else {
        int j = (gb - 2048) * 256 + tid;
        if (j >= DOUT) return;
        unsigned w0 = 0, w1 = 0, w2 = 0, w3 = 0;
        const float* r = W2 + (size_t)j * H;
        #pragma unroll 4
        for (int k = 0; k < 32; k++)  if (r[k]      >= 0.f) w0 |= (1u << k);
        #pragma unroll 4
        for (int k = 0; k < 32; k++)  if (r[32 + k] >= 0.f) w1 |= (1u << k);
        #pragma unroll 4
        for (int k = 0; k < 32; k++)  if (r[64 + k] >= 0.f) w2 |= (1u << k);
        #pragma unroll
        for (int k = 0; k < 4;  k++)  if (r[96 + k] >= 0.f) w3 |= (1u << k);
        g_w2p[j * 4 + 0] = w0; g_w2p[j * 4 + 1] = w1;
        g_w2p[j * 4 + 2] = w2; g_w2p[j * 4 + 3] = w3;
    }
}

// ============================================================
// Kernel G: gemm1 via mma.sync fp16 2-split, 512 threads,
// N-split across warp halves; fused BN partials.
// ============================================================
__global__ void __launch_bounds__(512, 1)
gemm1_mma(const float* __restrict__ x, const float* __restrict__ b1) {
    extern __shared__ char smem[];
    const uint32_t sm_base = smem_u32(smem);
    const int tid  = threadIdx.x;
    const int warp = tid >> 5;         // 0..15
    const int lane = tid & 31;
    const int nh   = warp >> 3;        // 0: groups 0-6, 1: groups 7-12
    const int rw   = warp & 7;         // row-warp
    const int row0 = blockIdx.x * 128;

    float* sb1 = (float*)(smem + SB1_OFF);
    if (tid < 104) sb1[tid] = (tid < H) ? b1[tid] : 0.f;

    // ---- stage chunk 0 into buf 0 ----
    {
        const float* xp = x + (size_t)row0 * DIN;
        #pragma unroll
        for (int i = 0; i < 4; i++) {
            int idx = tid + i * 512;
            int r = idx >> 4, q = idx & 15;
            float4 v = __ldg((const float4*)(xp + (size_t)r * DIN + q * 4));
            uint2 hi, lo; split2(v, hi, lo);
            char* p = smem + r * PITCH_B + q * 8;
            *(uint2*)(p + 0 * SPLIT_SZ) = hi;
            *(uint2*)(p + 1 * SPLIT_SZ) = lo;
        }
        #pragma unroll
        for (int i = 0; i < 2; i++) {
            int idx = tid + i * 512;
            int r = idx >> 3, q = idx & 7;
            uint4 v = __ldg((const uint4*)((const char*)g_w1h +
                            (size_t)r * (DIN * 2) + q * 16));
            *(uint4*)(smem + B_OFF + r * PITCH_B + q * 16) = v;
        }
    }
    __syncthreads();

    float acc0[28], acc1[28];
    #pragma unroll
    for (int i = 0; i < 28; i++) { acc0[i] = 0.f; acc1[i] = 0.f; }

    const uint32_t a_loff = (uint32_t)((rw * 16 + (lane & 15)) * PITCH_B +
                                       (lane >> 4) * 16);
    const uint32_t b_loff = (uint32_t)(((lane >> 4) * 8 + (lane & 7)) * PITCH_B +
                                       ((lane >> 3) & 1) * 16);
    const uint32_t b_rowbase = (uint32_t)(nh * 56 * PITCH_B);
    const uint32_t b2_loff = (uint32_t)((48 + (lane & 7)) * PITCH_B +
                                        ((lane >> 3) & 1) * 16);

    for (int c = 0; c < NCHUNK; c++) {
        const int buf = c & 1;
        const uint32_t abase = sm_base + buf * BUF_SZ;

        // ---- prefetch LDGs for chunk c+1 ----
        float4 xv[4]; uint4 wv[2];
        if (c < NCHUNK - 1) {
            const float* xp = x + (size_t)row0 * DIN + (c + 1) * KC;
            #pragma unroll
            for (int i = 0; i < 4; i++) {
                int idx = tid + i * 512;
                int r = idx >> 4, q = idx & 15;
                xv[i] = __ldg((const float4*)(xp + (size_t)r * DIN + q * 4));
            }
            const char* wp = (const char*)g_w1h + (size_t)(c + 1) * 128;
            #pragma unroll
            for (int i = 0; i < 2; i++) {
                int idx = tid + i * 512;
                int r = idx >> 3, q = idx & 7;
                wv[i] = __ldg((const uint4*)(wp + (size_t)r * (DIN * 2) + q * 16));
            }
        }

        // ---- compute chunk c ----
        float* acc = buf ? acc1 : acc0;
        #pragma unroll
        for (int ks = 0; ks < 4; ks++) {
            uint32_t bf[14];
            #pragma unroll
            for (int gp = 0; gp < 3; gp++) {
                ldsm4(bf + 4 * gp, abase + B_OFF + b_rowbase +
                      gp * (16 * PITCH_B) + b_loff + ks * 32);
            }
            if (nh == 0)
                ldsm2(bf + 12, abase + B_OFF + b2_loff + ks * 32);
            #pragma unroll
            for (int s = 0; s < 2; s++) {
                uint32_t a[4];
                ldsm4(a, abase + s * SPLIT_SZ + a_loff + ks * 32);
                #pragma unroll
                for (int g = 0; g < 7; g++)
                    if (nh == 0 || g < 6)
                        mma16816(acc + g * 4, a, bf + 2 * g);
            }
        }

        __syncthreads();

        // ---- convert + STS chunk c+1 into buf^1 ----
        if (c < NCHUNK - 1) {
            char* base = smem + (buf ^ 1) * BUF_SZ;
            #pragma unroll
            for (int i = 0; i < 4; i++) {
                int idx = tid + i * 512;
                int r = idx >> 4, q = idx & 15;
                uint2 hi, lo; split2(xv[i], hi, lo);
                char* p = base + r * PITCH_B + q * 8;
                *(uint2*)(p + 0 * SPLIT_SZ) = hi;
                *(uint2*)(p + 1 * SPLIT_SZ) = lo;
            }
            #pragma unroll
            for (int i = 0; i < 2; i++) {
                int idx = tid + i * 512;
                int r = idx >> 3, q = idx & 7;
                *(uint4*)(base + B_OFF + r * PITCH_B + q * 16) = wv[i];
            }
        }
        __syncthreads();
    }

    // ---- epilogue: store h = acc0 + acc1 + b1 (cols < 100) ----
    const int gr = row0 + rw * 16 + (lane >> 2);
    const int cb = (lane & 3) * 2;
    #pragma unroll
    for (int g = 0; g < 7; g++) {
        if (nh == 1 && g >= 6) break;
        int c0 = (nh * 7 + g) * 8 + cb;
        if (c0 < H) {
            float2 lo, hi;
            lo.x = acc0[g*4+0] + acc1[g*4+0] + sb1[c0];
            lo.y = acc0[g*4+1] + acc1[g*4+1] + sb1[c0 + 1];
            hi.x = acc0[g*4+2] + acc1[g*4+2] + sb1[c0];
            hi.y = acc0[g*4+3] + acc1[g*4+3] + sb1[c0 + 1];
            *(float2*)(g_h + (size_t)gr * H + c0)       = lo;
            *(float2*)(g_h + (size_t)(gr + 8) * H + c0) = hi;
        }
    }

    // ---- fused BN pass 1 ----
    __syncthreads();
    float s = 0.f, s2 = 0.f;
    if (tid < 200) {
        int f = tid % 100;
        for (int rr = tid / 100; rr < 128; rr += 2) {
            float v = g_h[(size_t)(row0 + rr) * H + f];
            s += v;
            s2 = fmaf(v, v, s2);
        }
    }
    float* red = (float*)smem;
    if (tid < 200) { red[tid] = s; red[256 + tid] = s2; }
    __syncthreads();
    if (tid < 100) {
        g_part[blockIdx.x * 200 + tid]       = red[tid] + red[tid + 100];
        g_part[blockIdx.x * 200 + 100 + tid] = red[256 + tid] + red[356 + tid];
    }
}

// ============================================================
// Kernel S: finish batch-norm (one warp per feature)
// ============================================================
__global__ void bn_finish(const float* __restrict__ gamma,
                          const float* __restrict__ beta) {
    int f = blockIdx.x;
    int lane = threadIdx.x;
    float s = 0.f, s2 = 0.f;
    for (int c = lane; c < 256; c += 32) {
        s  += g_part[c * 200 + f];
        s2 += g_part[c * 200 + 100 + f];
    }
    #pragma unroll
    for (int off = 16; off > 0; off >>= 1) {
        s  += __shfl_xor_sync(0xffffffffu, s,  off);
        s2 += __shfl_xor_sync(0xffffffffu, s2, off);
    }
    if (lane == 0) {
        float mu  = s  * (1.f / B);
        float m2  = s2 * (1.f / B);
        float var = m2 - mu * mu;
        float sc  = gamma[f] * rsqrtf(var + BN_EPS);
        g_scale[f] = sc;
        g_shift[f] = fmaf(-mu, sc, beta[f]);
    }
}

// ============================================================
// Kernel H: head — 2 rows/warp sharing w-loads, byte-packed logits
// ============================================================
#define LOG2E 1.4426950408889634f
#define LN2   0.69314718055994531f

__global__ __launch_bounds__(256)
void head(const float* __restrict__ b2, float* __restrict__ out) {
    __shared__ uint4 sw4[DOUT];
    __shared__ float sb[DOUT];
    __shared__ float ssc[128], ssh[128];

    const int tid = threadIdx.x;
    for (int i = tid; i < DOUT; i += 256) {
        sw4[i] = ((const uint4*)g_w2p)[i];
        sb[i]  = b2[i];
    }
    if (tid < H) { ssc[tid] = g_scale[tid]; ssh[tid] = g_shift[tid]; }
    __syncthreads();

    const int lane = tid & 31;
    const int warp = tid >> 5;
    const int row0 = (blockIdx.x * 8 + warp) * 2;

    const float* h0 = g_h + (size_t)row0 * H;
    const float* h1 = h0 + H;

    bool q0 = fmaf(h0[lane],      ssc[lane],      ssh[lane])      >= 0.f;
    bool q1 = fmaf(h0[32 + lane], ssc[32 + lane], ssh[32 + lane]) >= 0.f;
    bool q2 = fmaf(h0[64 + lane], ssc[64 + lane], ssh[64 + lane]) >= 0.f;
    bool q3 = (lane < 4) && (fmaf(h0[96 + lane], ssc[96 + lane], ssh[96 + lane]) >= 0.f);
    unsigned a0 = __ballot_sync(0xffffffffu, q0);
    unsigned a1 = __ballot_sync(0xffffffffu, q1);
    unsigned a2 = __ballot_sync(0xffffffffu, q2);
    unsigned a3 = __ballot_sync(0xffffffffu, q3);

    q0 = fmaf(h1[lane],      ssc[lane],      ssh[lane])      >= 0.f;
    q1 = fmaf(h1[32 + lane], ssc[32 + lane], ssh[32 + lane]) >= 0.f;
    q2 = fmaf(h1[64 + lane], ssc[64 + lane], ssh[64 + lane]) >= 0.f;
    q3 = (lane < 4) && (fmaf(h1[96 + lane], ssc[96 + lane], ssh[96 + lane]) >= 0.f);
    unsigned c0 = __ballot_sync(0xffffffffu, q0);
    unsigned c1 = __ballot_sync(0xffffffffu, q1);
    unsigned c2 = __ballot_sync(0xffffffffu, q2);
    unsigned c3 = __ballot_sync(0xffffffffu, q3);

    // ---- pass A: popc -> packed int8 logits, track max ----
    uint32_t pk0[8], pk1[8];
    float mx0 = -1e30f, mx1 = -1e30f;
    #pragma unroll
    for (int i = 0; i < 8; i++) {
        pk0[i] = 0; pk1[i] = 0;
        int jb = i * 128 + lane * 4;
        if (jb < DOUT) {
            float4 bias = *(const float4*)&sb[jb];
            #pragma unroll
            for (int q = 0; q < 4; q++) {
                uint4 w = sw4[jb + q];
                int p0 = __popc(a0 ^ w.x) + __popc(a1 ^ w.y) +
                         __popc(a2 ^ w.z) + __popc(a3 ^ w.w);
                int p1 = __popc(c0 ^ w.x) + __popc(c1 ^ w.y) +
                         __popc(c2 ^ w.z) + __popc(c3 ^ w.w);
                int v0 = H - 2 * p0;
                int v1 = H - 2 * p1;
                pk0[i] |= (uint32_t)(v0 & 255) << (8 * q);
                pk1[i] |= (uint32_t)(v1 & 255) << (8 * q);
                float bi = (q == 0) ? bias.x : (q == 1) ? bias.y :
                           (q == 2) ? bias.z : bias.w;
                mx0 = fmaxf(mx0, (float)v0 + bi);
                mx1 = fmaxf(mx1, (float)v1 + bi);
            }
        }
    }
    #pragma unroll
    for (int off = 16; off > 0; off >>= 1) {
        mx0 = fmaxf(mx0, __shfl_xor_sync(0xffffffffu, mx0, off));
        mx1 = fmaxf(mx1, __shfl_xor_sync(0xffffffffu, mx1, off));
    }

    // ---- pass B: sum exp ----
    float s0 = 0.f, s1 = 0.f;
    #pragma unroll
    for (int i = 0; i < 8; i++) {
        int jb = i * 128 + lane * 4;
        if (jb < DOUT) {
            float4 bias = *(const float4*)&sb[jb];
            #pragma unroll
            for (int q = 0; q < 4; q++) {
                float bi = (q == 0) ? bias.x : (q == 1) ? bias.y :
                           (q == 2) ? bias.z : bias.w;
                int v0 = (int)(signed char)((pk0[i] >> (8 * q)) & 0xffu);
                int v1 = (int)(signed char)((pk1[i] >> (8 * q)) & 0xffu);
                s0 += exp2f(((float)v0 + bi - mx0) * LOG2E);
                s1 += exp2f(((float)v1 + bi - mx1) * LOG2E);
            }
        }
    }
    #pragma unroll
    for (int off = 16; off > 0; off >>= 1) {
        s0 += __shfl_xor_sync(0xffffffffu, s0, off);
        s1 += __shfl_xor_sync(0xffffffffu, s1, off);
    }
    float lse0 = fmaf(LN2, __log2f(s0), mx0);
    float lse1 = fmaf(LN2, __log2f(s1), mx1);

    // ---- pass C: store ----
    float* o0 = out + (size_t)row0 * DOUT;
    float* o1 = o0 + DOUT;
    #pragma unroll
    for (int i = 0; i < 8; i++) {
        int jb = i * 128 + lane * 4;
        if (jb < DOUT) {
            float4 bias = *(const float4*)&sb[jb];
            float4 r0, r1;
            {
                int v = (int)(signed char)((pk0[i]) & 0xffu);
                r0.x = (float)v + bias.x - lse0;
                v = (int)(signed char)((pk0[i] >> 8) & 0xffu);
                r0.y = (float)v + bias.y - lse0;
                v = (int)(signed char)((pk0[i] >> 16) & 0xffu);
                r0.z = (float)v + bias.z - lse0;
                v = (int)(signed char)((pk0[i] >> 24) & 0xffu);
                r0.w = (float)v + bias.w - lse0;
            }
            {
                int v = (int)(signed char)((pk1[i]) & 0xffu);
                r1.x = (float)v + bias.x - lse1;
                v = (int)(signed char)((pk1[i] >> 8) & 0xffu);
                r1.y = (float)v + bias.y - lse1;
                v = (int)(signed char)((pk1[i] >> 16) & 0xffu);
                r1.z = (float)v + bias.z - lse1;
                v = (int)(signed char)((pk1[i] >> 24) & 0xffu);
                r1.w = (float)v + bias.w - lse1;
            }
            *(float4*)(o0 + jb) = r0;
            *(float4*)(o1 + jb) = r1;
        }
    }
}

// ============================================================
// Launch
// ============================================================
extern "C" void kernel_launch(void* const* d_in, const int* in_sizes, int n_in,
                              void* d_out, int out_size) {
    (void)in_sizes; (void)n_in; (void)out_size;
    const float* x     = (const float*)d_in[0];
    const float* W1    = (const float*)d_in[1];
    const float* b1    = (const float*)d_in[2];
    const float* gamma = (const float*)d_in[3];
    const float* beta  = (const float*)d_in[4];
    const float* W2    = (const float*)d_in[5];
    const float* b2    = (const float*)d_in[6];
    float* out = (float*)d_out;

    static int smem_set = 0;
    if (!smem_set) {
        cudaFuncSetAttribute(gemm1_mma, cudaFuncAttributeMaxDynamicSharedMemorySize,
                             SMEM_TOTAL);
        smem_set = 1;
    }

    pack_all<<<2052, 256>>>(W1, W2);
    gemm1_mma<<<B / 128, 512, SMEM_TOTAL>>>(x, b1);
    bn_finish<<<H, 32>>>(gamma, beta);
    head<<<B / 16, 256>>>(b2, out);
}

// round 6
// speedup vs baseline: 1.2674x; 1.2674x over previous
#include <cuda_runtime.h>
#include <cuda_fp16.h>
#include <cstdint>

#define B    32768
#define DIN  4096
#define H    100
#define DOUT 1000
#define BN_EPS 1e-4f

#define KC      64                 // K per chunk
#define NCHUNK  (DIN / KC)         // 64
#define NPAD    128                // padded feature rows in g_w1h
#define NG      13                 // n8 groups (N=104 >= 100)

// padded smem tile geometry (fp16: 64 elems = 128B + 16B pad)
#define PITCH_B   144
#define SPLIT_SZ  (128 * PITCH_B)  // 18432
#define BUF_SZ    (3 * SPLIT_SZ)   // A-hi, A-lo, B = 55296
#define B_OFF     (2 * SPLIT_SZ)
#define SB1_OFF   (2 * BUF_SZ)     // b1 staging
#define SMEM_TOTAL (2 * BUF_SZ + 512)

// ---- scratch (no allocations allowed) ----
__device__ float     g_h[(size_t)B * H];
__device__ float     g_scale[H];
__device__ float     g_shift[H];
__device__ unsigned  g_w2p[DOUT * 4];
__device__ __half    g_w1h[(size_t)NPAD * DIN];  // sign(W1) fp16, rows 100..127 = 0
__device__ float     g_part[256 * 200];          // per-CTA BN partials [s|s2]

// ============================================================
// helpers
// ============================================================
__device__ __forceinline__ uint32_t smem_u32(const void* p) {
    uint32_t a;
    asm("{ .reg .u64 t; cvta.to.shared.u64 t, %1; cvt.u32.u64 %0, t; }"
        : "=r"(a) : "l"(p));
    return a;
}
__device__ __forceinline__ void ldsm4(uint32_t* r, uint32_t addr) {
    asm volatile("ldmatrix.sync.aligned.m8n8.x4.shared.b16 {%0,%1,%2,%3}, [%4];"
                 : "=r"(r[0]), "=r"(r[1]), "=r"(r[2]), "=r"(r[3]) : "r"(addr));
}
__device__ __forceinline__ void ldsm2(uint32_t* r, uint32_t addr) {
    asm volatile("ldmatrix.sync.aligned.m8n8.x2.shared.b16 {%0,%1}, [%2];"
                 : "=r"(r[0]), "=r"(r[1]) : "r"(addr));
}
__device__ __forceinline__ void mma16816(float* d, const uint32_t* a,
                                         const uint32_t* b) {
    asm volatile(
        "mma.sync.aligned.m16n8k16.row.col.f32.f16.f16.f32 "
        "{%0,%1,%2,%3}, {%4,%5,%6,%7}, {%8,%9}, {%0,%1,%2,%3};"
        : "+f"(d[0]), "+f"(d[1]), "+f"(d[2]), "+f"(d[3])
        : "r"(a[0]), "r"(a[1]), "r"(a[2]), "r"(a[3]), "r"(b[0]), "r"(b[1]));
}
// exact 2-way fp16 split
__device__ __forceinline__ void split2(float4 v, uint2& hi, uint2& lo) {
    __half2 a = __floats2half2_rn(v.x, v.y);
    __half2 b = __floats2half2_rn(v.z, v.w);
    float2 fa = __half22float2(a), fb = __half22float2(b);
    __half2 c = __floats2half2_rn(v.x - fa.x, v.y - fa.y);
    __half2 d = __floats2half2_rn(v.z - fb.x, v.w - fb.y);
    hi = make_uint2(*(uint32_t*)&a, *(uint32_t*)&b);
    lo = make_uint2(*(uint32_t*)&c, *(uint32_t*)&d);
}

// ============================================================
// Kernel P: fused packing of sign(W1)->fp16 and sign(W2)->bitmask
// ============================================================
__global__ void pack_all(const float* __restrict__ W1,
                         const float* __restrict__ W2) {
    int gb = blockIdx.x;
    int tid = threadIdx.x;
    if (gb < 2048) {
        int idx = gb * 256 + tid;
        int row = idx >> 12;
        int col = idx & 4095;
        float v = 0.f;
        if (row < H) v = (W1[(size_t)row * DIN + col] >= 0.f) ? 1.f : -1.f;
        g_w1h[(size_t)row * DIN + col] = __float2half(v);
    } else {
        int j = (gb - 2048) * 256 + tid;
        if (j >= DOUT) return;
        unsigned w0 = 0, w1 = 0, w2 = 0, w3 = 0;
        const float* r = W2 + (size_t)j * H;
        #pragma unroll 4
        for (int k = 0; k < 32; k++)  if (r[k]      >= 0.f) w0 |= (1u << k);
        #pragma unroll 4
        for (int k = 0; k < 32; k++)  if (r[32 + k] >= 0.f) w1 |= (1u << k);
        #pragma unroll 4
        for (int k = 0; k < 32; k++)  if (r[64 + k] >= 0.f) w2 |= (1u << k);
        #pragma unroll
        for (int k = 0; k < 4;  k++)  if (r[96 + k] >= 0.f) w3 |= (1u << k);
        g_w2p[j * 4 + 0] = w0; g_w2p[j * 4 + 1] = w1;
        g_w2p[j * 4 + 2] = w2; g_w2p[j * 4 + 3] = w3;
    }
}

// ============================================================
// Kernel G: gemm1 via mma.sync fp16 2-split (R4 measured-best),
// 256 threads, fused BN partials.
// ============================================================
__global__ void __launch_bounds__(256, 1)
gemm1_mma(const float* __restrict__ x, const float* __restrict__ b1) {
    extern __shared__ char smem[];
    const uint32_t sm_base = smem_u32(smem);
    const int tid  = threadIdx.x;
    const int warp = tid >> 5;
    const int lane = tid & 31;
    const int row0 = blockIdx.x * 128;

    float* sb1 = (float*)(smem + SB1_OFF);
    if (tid < 104) sb1[tid] = (tid < H) ? b1[tid] : 0.f;

    // ---- stage chunk 0 into buf 0 ----
    {
        const float* xp = x + (size_t)row0 * DIN;
        #pragma unroll
        for (int i = 0; i < 8; i++) {
            int idx = tid + i * 256;
            int r = idx >> 4, q = idx & 15;
            float4 v = __ldg((const float4*)(xp + (size_t)r * DIN + q * 4));
            uint2 hi, lo; split2(v, hi, lo);
            char* p = smem + r * PITCH_B + q * 8;
            *(uint2*)(p + 0 * SPLIT_SZ) = hi;
            *(uint2*)(p + 1 * SPLIT_SZ) = lo;
        }
        #pragma unroll
        for (int i = 0; i < 4; i++) {
            int idx = tid + i * 256;
            int r = idx >> 3, q = idx & 7;
            uint4 v = __ldg((const uint4*)((const char*)g_w1h +
                            (size_t)r * (DIN * 2) + q * 16));
            *(uint4*)(smem + B_OFF + r * PITCH_B + q * 16) = v;
        }
    }
    __syncthreads();

    float acc0[NG * 4], acc1[NG * 4];
    #pragma unroll
    for (int i = 0; i < NG * 4; i++) { acc0[i] = 0.f; acc1[i] = 0.f; }

    const uint32_t a_loff = (uint32_t)((warp * 16 + (lane & 15)) * PITCH_B +
                                       ((lane >> 4) * 8) * 2);
    const uint32_t b_loff = (uint32_t)(((lane >> 4) * 8 + (lane & 7)) * PITCH_B +
                                       (((lane >> 3) & 1) * 8) * 2);

    for (int c = 0; c < NCHUNK; c++) {
        const int buf = c & 1;
        const uint32_t abase = sm_base + buf * BUF_SZ;

        // ---- prefetch LDGs for chunk c+1 ----
        float4 xv[8]; uint4 wv[4];
        if (c < NCHUNK - 1) {
            const float* xp = x + (size_t)row0 * DIN + (c + 1) * KC;
            #pragma unroll
            for (int i = 0; i < 8; i++) {
                int idx = tid + i * 256;
                int r = idx >> 4, q = idx & 15;
                xv[i] = __ldg((const float4*)(xp + (size_t)r * DIN + q * 4));
            }
            const char* wp = (const char*)g_w1h + (size_t)(c + 1) * 128;
            #pragma unroll
            for (int i = 0; i < 4; i++) {
                int idx = tid + i * 256;
                int r = idx >> 3, q = idx & 7;
                wv[i] = __ldg((const uint4*)(wp + (size_t)r * (DIN * 2) + q * 16));
            }
        }

        // ---- compute chunk c ----
        float* acc = buf ? acc1 : acc0;
        #pragma unroll
        for (int ks = 0; ks < 4; ks++) {
            uint32_t bf[NG * 2];
            #pragma unroll
            for (int gp = 0; gp < 6; gp++) {
                uint32_t addr = abase + B_OFF + gp * (16 * PITCH_B) +
                                b_loff + ks * 32;
                ldsm4(bf + 4 * gp, addr);
            }
            {
                uint32_t addr = abase + B_OFF + (96 + (lane & 7)) * PITCH_B +
                                (((lane >> 3) & 1) * 8) * 2 + ks * 32;
                ldsm2(bf + 24, addr);
            }
            #pragma unroll
            for (int s = 0; s < 2; s++) {
                uint32_t a[4];
                ldsm4(a, abase + s * SPLIT_SZ + a_loff + ks * 32);
                #pragma unroll
                for (int g = 0; g < NG; g++)
                    mma16816(acc + g * 4, a, bf + 2 * g);
            }
        }

        __syncthreads();

        // ---- convert + STS chunk c+1 into buf^1 ----
        if (c < NCHUNK - 1) {
            char* base = smem + (buf ^ 1) * BUF_SZ;
            #pragma unroll
            for (int i = 0; i < 8; i++) {
                int idx = tid + i * 256;
                int r = idx >> 4, q = idx & 15;
                uint2 hi, lo; split2(xv[i], hi, lo);
                char* p = base + r * PITCH_B + q * 8;
                *(uint2*)(p + 0 * SPLIT_SZ) = hi;
                *(uint2*)(p + 1 * SPLIT_SZ) = lo;
            }
            #pragma unroll
            for (int i = 0; i < 4; i++) {
                int idx = tid + i * 256;
                int r = idx >> 3, q = idx & 7;
                *(uint4*)(base + B_OFF + r * PITCH_B + q * 16) = wv[i];
            }
        }
        __syncthreads();
    }

    // ---- epilogue: store h = acc0 + acc1 + b1 (cols < 100) ----
    const int gr = row0 + warp * 16 + (lane >> 2);
    const int cb = (lane & 3) * 2;
    #pragma unroll
    for (int g = 0; g < NG; g++) {
        int c0 = g * 8 + cb;
        if (c0 < H) {
            float2 lo, hi;
            lo.x = acc0[g*4+0] + acc1[g*4+0] + sb1[c0];
            lo.y = acc0[g*4+1] + acc1[g*4+1] + sb1[c0 + 1];
            hi.x = acc0[g*4+2] + acc1[g*4+2] + sb1[c0];
            hi.y = acc0[g*4+3] + acc1[g*4+3] + sb1[c0 + 1];
            *(float2*)(g_h + (size_t)gr * H + c0)       = lo;
            *(float2*)(g_h + (size_t)(gr + 8) * H + c0) = hi;
        }
    }

    // ---- fused BN pass 1: per-CTA partial sums over its 128 rows ----
    __threadfence_block();
    __syncthreads();
    float s = 0.f, s2 = 0.f;
    if (tid < 200) {
        int f = tid % 100;
        for (int rr = tid / 100; rr < 128; rr += 2) {
            float v = g_h[(size_t)(row0 + rr) * H + f];
            s += v;
            s2 = fmaf(v, v, s2);
        }
    }
    float* red = (float*)smem;
    if (tid < 200) { red[tid] = s; red[256 + tid] = s2; }
    __syncthreads();
    if (tid < 100) {
        g_part[blockIdx.x * 200 + tid]       = red[tid] + red[tid + 100];
        g_part[blockIdx.x * 200 + 100 + tid] = red[256 + tid] + red[356 + tid];
    }
}

// ============================================================
// Kernel S: finish batch-norm (one warp per feature)
// ============================================================
__global__ void bn_finish(const float* __restrict__ gamma,
                          const float* __restrict__ beta) {
    int f = blockIdx.x;
    int lane = threadIdx.x;
    float s = 0.f, s2 = 0.f;
    for (int c = lane; c < 256; c += 32) {
        s  += g_part[c * 200 + f];
        s2 += g_part[c * 200 + 100 + f];
    }
    #pragma unroll
    for (int off = 16; off > 0; off >>= 1) {
        s  += __shfl_xor_sync(0xffffffffu, s,  off);
        s2 += __shfl_xor_sync(0xffffffffu, s2, off);
    }
    if (lane == 0) {
        float mu  = s  * (1.f / B);
        float m2  = s2 * (1.f / B);
        float var = m2 - mu * mu;
        float sc  = gamma[f] * rsqrtf(var + BN_EPS);
        g_scale[f] = sc;
        g_shift[f] = fmaf(-mu, sc, beta[f]);
    }
}

// ============================================================
// Kernel H: head (R3 measured-best) — one row/warp, o[32] regs
// ============================================================
__global__ __launch_bounds__(256)
void head(const float* __restrict__ b2, float* __restrict__ out) {
    __shared__ unsigned sw[DOUT * 4];
    __shared__ float    sb[DOUT];
    __shared__ float    ssc[H], ssh[H];

    const int tid = threadIdx.x;
    for (int i = tid; i < DOUT * 4; i += 256) sw[i] = g_w2p[i];
    for (int i = tid; i < DOUT;     i += 256) sb[i] = b2[i];
    if (tid < H) { ssc[tid] = g_scale[tid]; ssh[tid] = g_shift[tid]; }
    __syncthreads();

    const int lane = tid & 31;
    const int warp = tid >> 5;
    const int row  = blockIdx.x * 8 + warp;

    const float* hr = g_h + (size_t)row * H;
    bool p0 = fmaf(hr[lane],      ssc[lane],      ssh[lane])      >= 0.f;
    bool p1 = fmaf(hr[32 + lane], ssc[32 + lane], ssh[32 + lane]) >= 0.f;
    bool p2 = fmaf(hr[64 + lane], ssc[64 + lane], ssh[64 + lane]) >= 0.f;
    bool p3 = (lane < 4) ?
              (fmaf(hr[96 + lane], ssc[96 + lane], ssh[96 + lane]) >= 0.f) : false;
    unsigned a0 = __ballot_sync(0xffffffffu, p0);
    unsigned a1 = __ballot_sync(0xffffffffu, p1);
    unsigned a2 = __ballot_sync(0xffffffffu, p2);
    unsigned a3 = __ballot_sync(0xffffffffu, p3);

    float o[32];
    float mx = -1e30f;
    #pragma unroll
    for (int i = 0; i < 32; i++) {
        int j = i * 32 + lane;
        if (j < DOUT) {
            uint4 w = *(const uint4*)&sw[j * 4];
            int p = __popc(a0 ^ w.x) + __popc(a1 ^ w.y) +
                    __popc(a2 ^ w.z) + __popc(a3 ^ w.w);
            o[i] = (float)(H - 2 * p) + sb[j];
            mx = fmaxf(mx, o[i]);
        } else {
            o[i] = -1e30f;
        }
    }
    #pragma unroll
    for (int off = 16; off > 0; off >>= 1)
        mx = fmaxf(mx, __shfl_xor_sync(0xffffffffu, mx, off));

    float s = 0.f;
    #pragma unroll
    for (int i = 0; i < 32; i++)
        s += exp2f((o[i] - mx) * 1.4426950408889634f);
    #pragma unroll
    for (int off = 16; off > 0; off >>= 1)
        s += __shfl_xor_sync(0xffffffffu, s, off);

    float lse = fmaf(0.69314718055994531f, __log2f(s), mx);

    float* orow = out + (size_t)row * DOUT;
    #pragma unroll
    for (int i = 0; i < 32; i++) {
        int j = i * 32 + lane;
        if (j < DOUT) orow[j] = o[i] - lse;
    }
}

// ============================================================
// Launch
// ============================================================
extern "C" void kernel_launch(void* const* d_in, const int* in_sizes, int n_in,
                              void* d_out, int out_size) {
    (void)in_sizes; (void)n_in; (void)out_size;
    const float* x     = (const float*)d_in[0];
    const float* W1    = (const float*)d_in[1];
    const float* b1    = (const float*)d_in[2];
    const float* gamma = (const float*)d_in[3];
    const float* beta  = (const float*)d_in[4];
    const float* W2    = (const float*)d_in[5];
    const float* b2    = (const float*)d_in[6];
    float* out = (float*)d_out;

    static int smem_set = 0;
    if (!smem_set) {
        cudaFuncSetAttribute(gemm1_mma, cudaFuncAttributeMaxDynamicSharedMemorySize,
                             SMEM_TOTAL);
        smem_set = 1;
    }

    pack_all<<<2052, 256>>>(W1, W2);
    gemm1_mma<<<B / 128, 256, SMEM_TOTAL>>>(x, b1);
    bn_finish<<<H, 32>>>(gamma, beta);
    head<<<B / 8, 256>>>(b2, out);
}